// round 1
// baseline (speedup 1.0000x reference)
#include <cuda_runtime.h>

// CapsuleLayer dynamic routing, GB300 sm_103a.
// Shapes (hardcoded from reference): B=64, I=2048, Din=16, J=32, D=32, 3 routing iters.
//
// Algebraic restructuring: routing logits b_k[b,j,i] = osum_k[b,j,:] . u_hat[b,j,i,:]
// where osum_k = sum of squashed outputs of previous iterations (osum_0 = 0).
// So each routing iteration is one fused streaming pass over u_hat:
//   c = softmax_j(osum . u_hat); s[b,j,d] = sum_i c[b,j,i]*u_hat[b,j,i,d]
// followed by a tiny squash + osum-update kernel. No b tensor ever stored.

#define BB 64
#define II 2048
#define CC 16     // Din
#define JJ 32
#define DD 32
#define NTILE 16  // i-tiles for routing partials
#define IPB 128   // i per routing block
#define IPW 16    // i per warp (8 warps/block)

typedef unsigned long long u64;

// u_hat stored as [b][i][j][d] so each (b,i) slice (32x32 = 4KB) is contiguous.
__device__ float g_U[(size_t)BB * II * JJ * DD];        // 512 MB scratch
__device__ float g_osum[BB * JJ * DD];                  // running sum of outputs
__device__ float g_spart[NTILE][BB * JJ * DD];          // per-itile partial s

// ---------- packed fp32x2 helpers (2x FFMA throughput on sm_103a) ----------
__device__ __forceinline__ u64 fma2(u64 a, u64 b, u64 c) {
    u64 d;
    asm("fma.rn.f32x2 %0, %1, %2, %3;" : "=l"(d) : "l"(a), "l"(b), "l"(c));
    return d;
}
__device__ __forceinline__ float hsum2(u64 v) {
    float a, b;
    asm("mov.b64 {%0, %1}, %2;" : "=f"(a), "=f"(b) : "l"(v));
    return a + b;
}

// ---------------------------------------------------------------------------
// Kernel A: u_hat[b][i][j][d] = sum_c W[j][i][d][c] * x[b][i][c]
// One block per i. W[:,i,:,:] (64KB) staged in smem, reused by all 64 batches.
// Thread (b = t>>2, q = t&3) computes d in [q*8, q*8+8) for all j.
// Writes: per (j) two STG.128 per thread -> warp covers 8 b-rows x 128B, fully
// coalesced at line granularity.
// ---------------------------------------------------------------------------
__global__ void __launch_bounds__(256) uhat_kernel(const float* __restrict__ x,
                                                   const float* __restrict__ W) {
    extern __shared__ float sm[];
    float* sW = sm;                 // [32][32][16] = 16384 floats
    float* sX = sm + JJ * DD * CC;  // [64][16]     = 1024 floats
    const int i = blockIdx.x;
    const int t = threadIdx.x;

    // Load W slice: per j a contiguous 512-float block at (j*II+i)*512.
    const float4* Wg = reinterpret_cast<const float4*>(W);
    #pragma unroll
    for (int v = t; v < JJ * DD * CC / 4; v += 256) {
        int j = v >> 7, r = v & 127;
        reinterpret_cast<float4*>(sW)[v] = Wg[(size_t)(j * II + i) * 128 + r];
    }
    // Load x slice: per b 16 floats at (b*II+i)*16.
    const float4* Xg = reinterpret_cast<const float4*>(x);
    if (t < BB * CC / 4) {
        int b = t >> 2, r = t & 3;
        reinterpret_cast<float4*>(sX)[t] = Xg[(size_t)(b * II + i) * 4 + r];
    }
    __syncthreads();

    const int b = t >> 2, q = t & 3;
    u64 xr[8];
    {
        const u64* xp = reinterpret_cast<const u64*>(sX + b * CC);
        #pragma unroll
        for (int k = 0; k < 8; k++) xr[k] = xp[k];
    }
    float* ub = g_U + ((size_t)b * II + i) * (JJ * DD);

    #pragma unroll 4
    for (int j = 0; j < JJ; j++) {
        float acc[8];
        #pragma unroll
        for (int dd = 0; dd < 8; dd++) {
            const u64* wp =
                reinterpret_cast<const u64*>(sW + (j * DD + q * 8 + dd) * CC);
            u64 a0 = 0ULL, a1 = 0ULL;
            #pragma unroll
            for (int k = 0; k < 8; k += 2) {
                a0 = fma2(wp[k],     xr[k],     a0);
                a1 = fma2(wp[k + 1], xr[k + 1], a1);
            }
            acc[dd] = hsum2(a0) + hsum2(a1);
        }
        float4* o = reinterpret_cast<float4*>(ub + j * DD + q * 8);
        o[0] = make_float4(acc[0], acc[1], acc[2], acc[3]);
        o[1] = make_float4(acc[4], acc[5], acc[6], acc[7]);
    }
}

// ---------------------------------------------------------------------------
// Kernel B: one fused routing pass.
// grid = (NTILE, BB); 256 threads (8 warps), each warp handles 16 consecutive i.
// Lane layout: float4 chunk q*32+l of the 1024-float (j,d) tile -> lane l, chunk
// q holds j = 4q + (l>>3), d-segment 4*(l&7)..+3. Logits reduced within
// 8-lane groups, softmax over all 32 j via xor-8/xor-16 shuffles.
// Per-warp accumulators stay in registers; block reduce is fixed-order
// (deterministic), written to per-itile partials (no atomics).
// ---------------------------------------------------------------------------
__global__ void __launch_bounds__(256) route_kernel() {
    __shared__ float sS[8][JJ * DD];  // 32 KB
    const int itile = blockIdx.x, b = blockIdx.y;
    const int t = threadIdx.x, w = t >> 5, l = t & 31;

    float4 ov[8];
    {
        const float4* op = reinterpret_cast<const float4*>(g_osum + b * (JJ * DD));
        #pragma unroll
        for (int q = 0; q < 8; q++) ov[q] = op[q * 32 + l];
    }
    float4 sacc[8];
    #pragma unroll
    for (int q = 0; q < 8; q++) sacc[q] = make_float4(0.f, 0.f, 0.f, 0.f);

    const int i0 = itile * IPB + w * IPW;
    for (int n = 0; n < IPW; n++) {
        const int i = i0 + n;
        const float4* up =
            reinterpret_cast<const float4*>(g_U + ((size_t)b * II + i) * (JJ * DD));
        float4 uv[8];
        #pragma unroll
        for (int q = 0; q < 8; q++) uv[q] = up[q * 32 + l];

        // partial logits (4 d's each), then reduce across the 8 lanes that
        // share the same j-set
        float tp[8];
        #pragma unroll
        for (int q = 0; q < 8; q++)
            tp[q] = uv[q].x * ov[q].x + uv[q].y * ov[q].y +
                    uv[q].z * ov[q].z + uv[q].w * ov[q].w;
        #pragma unroll
        for (int s = 1; s < 8; s <<= 1) {
            #pragma unroll
            for (int q = 0; q < 8; q++)
                tp[q] += __shfl_xor_sync(0xffffffffu, tp[q], s);
        }
        // softmax over all 32 j (lane group g = l>>3 holds j = 4q+g)
        float m = tp[0];
        #pragma unroll
        for (int q = 1; q < 8; q++) m = fmaxf(m, tp[q]);
        m = fmaxf(m, __shfl_xor_sync(0xffffffffu, m, 8));
        m = fmaxf(m, __shfl_xor_sync(0xffffffffu, m, 16));
        float e[8];
        float ssum = 0.f;
        #pragma unroll
        for (int q = 0; q < 8; q++) {
            e[q] = __expf(tp[q] - m);
            ssum += e[q];
        }
        ssum += __shfl_xor_sync(0xffffffffu, ssum, 8);
        ssum += __shfl_xor_sync(0xffffffffu, ssum, 16);
        float inv = 1.0f / ssum;
        #pragma unroll
        for (int q = 0; q < 8; q++) {
            float cq = e[q] * inv;
            sacc[q].x += cq * uv[q].x;
            sacc[q].y += cq * uv[q].y;
            sacc[q].z += cq * uv[q].z;
            sacc[q].w += cq * uv[q].w;
        }
    }

    #pragma unroll
    for (int q = 0; q < 8; q++)
        reinterpret_cast<float4*>(sS[w])[q * 32 + l] = sacc[q];
    __syncthreads();
    for (int idx = t; idx < JJ * DD; idx += 256) {
        float v = sS[0][idx] + sS[1][idx] + sS[2][idx] + sS[3][idx] +
                  sS[4][idx] + sS[5][idx] + sS[6][idx] + sS[7][idx];
        g_spart[itile][b * (JJ * DD) + idx] = v;
    }
}

// ---------------------------------------------------------------------------
// Kernel C: reduce itile partials, squash, update osum (or write final out).
// One warp per (b,j); lane = d. Fixed reduction order -> deterministic.
// ---------------------------------------------------------------------------
__global__ void __launch_bounds__(256) squash_kernel(float* __restrict__ out,
                                                     int last) {
    const int t = threadIdx.x;
    const int bj = blockIdx.x * 8 + (t >> 5);
    const int l = t & 31;
    float v = 0.f;
    #pragma unroll
    for (int it = 0; it < NTILE; it++) v += g_spart[it][bj * DD + l];
    float s2 = v * v;
    #pragma unroll
    for (int s = 1; s < 32; s <<= 1) s2 += __shfl_xor_sync(0xffffffffu, s2, s);
    float scale = (s2 / (1.0f + s2)) * rsqrtf(s2 + 1e-7f);
    float o = scale * v;
    if (last)
        out[bj * DD + l] = o;
    else
        g_osum[bj * DD + l] += o;
}

__global__ void __launch_bounds__(256) zero_osum_kernel() {
    int idx = blockIdx.x * 256 + threadIdx.x;
    if (idx < BB * JJ * DD) g_osum[idx] = 0.f;
}

// ---------------------------------------------------------------------------
extern "C" void kernel_launch(void* const* d_in, const int* in_sizes, int n_in,
                              void* d_out, int out_size) {
    const float* x;
    const float* W;
    if (in_sizes[0] == BB * II * CC) {
        x = (const float*)d_in[0];
        W = (const float*)d_in[1];
    } else {
        x = (const float*)d_in[1];
        W = (const float*)d_in[0];
    }

    const int smem_bytes = (JJ * DD * CC + BB * CC) * (int)sizeof(float);  // 69632
    cudaFuncSetAttribute(uhat_kernel, cudaFuncAttributeMaxDynamicSharedMemorySize,
                         smem_bytes);

    zero_osum_kernel<<<(BB * JJ * DD + 255) / 256, 256>>>();
    uhat_kernel<<<II, 256, smem_bytes>>>(x, W);
    for (int k = 0; k < 3; k++) {
        route_kernel<<<dim3(NTILE, BB), 256>>>();
        squash_kernel<<<BB * JJ / 8, 256>>>((float*)d_out, (k == 2) ? 1 : 0);
    }
}

// round 2
// speedup vs baseline: 4.2052x; 4.2052x over previous
#include <cuda_runtime.h>
#include <cuda_fp16.h>

// CapsuleLayer dynamic routing, GB300 sm_103a.
// B=64, I=2048, Din=16, J=32, D=32, 3 routing iters.
//
// b_k[b,j,i] = osum_k[b,j,:] . u_hat[b,j,i,:], osum_k = sum of prior squashed
// outputs. Each routing iteration = one streaming pass over u_hat (stored fp16,
// layout [b][i][j][d]), followed by tiny squash/osum-update.
// Iteration 0 has c == 1/32 exactly (softmax of zeros) -> pure streaming sum.

#define BB 64
#define II 2048
#define CC 16     // Din
#define JJ 32
#define DD 32
#define NTILE 16  // i-tiles for routing partials
#define IPB 128   // i per routing block
#define IPW 16    // i per warp (8 warps/block)

typedef unsigned long long u64;

__device__ __half g_U[(size_t)BB * II * JJ * DD];   // 256 MB scratch (fp16)
__device__ float g_osum[BB * JJ * DD];              // running output sum
__device__ float g_spart[NTILE][BB * JJ * DD];      // per-itile partial s

// ---------- packed fp32x2 helpers (2x fp32 throughput on sm_103a) ----------
__device__ __forceinline__ u64 fma2(u64 a, u64 b, u64 c) {
    u64 d;
    asm("fma.rn.f32x2 %0, %1, %2, %3;" : "=l"(d) : "l"(a), "l"(b), "l"(c));
    return d;
}
__device__ __forceinline__ u64 add2(u64 a, u64 b) {
    u64 d;
    asm("add.rn.f32x2 %0, %1, %2;" : "=l"(d) : "l"(a), "l"(b));
    return d;
}
__device__ __forceinline__ float hsum2(u64 v) {
    float a, b;
    asm("mov.b64 {%0, %1}, %2;" : "=f"(a), "=f"(b) : "l"(v));
    return a + b;
}

// ---------------------------------------------------------------------------
// Kernel A: u_hat[b][i][j][d] = sum_c W[j][i][d][c] * x[b][i][c], stored fp16.
// One block per i. W slice staged in smem (rows padded to stride 18 floats for
// conflict-light LDS.64). Thread (bg = t>>4, q = t&15) handles 4 batches
// (b = bg + 16s) and 2 d's (d = 2q, 2q+1) -> W LDS amortized over 4 batches.
// ---------------------------------------------------------------------------
__global__ void __launch_bounds__(256, 2)
uhat_kernel(const float* __restrict__ x, const float* __restrict__ W) {
    extern __shared__ float sm[];
    float* sW = sm;                // [1024 rows][18]
    float* sX = sm + 1024 * 18;    // [64][16]
    const int i = blockIdx.x;
    const int t = threadIdx.x;

    // Stage W slice (64KB), coalesced float4 reads, padded scalar stores.
    const float4* Wg = reinterpret_cast<const float4*>(W);
    #pragma unroll
    for (int k = 0; k < 16; k++) {
        int v = t + 256 * k;          // 0..4095
        int row = v >> 2, ch = v & 3; // row = j*32 + d
        int j = row >> 5, d = row & 31;
        float4 f = Wg[(size_t)(j * II + i) * 128 + d * 4 + ch];
        float* p = sW + row * 18 + ch * 4;
        p[0] = f.x; p[1] = f.y; p[2] = f.z; p[3] = f.w;
    }
    // Stage x slice (all 64 b x 16 c).
    {
        int b = t >> 2, r = t & 3;
        reinterpret_cast<float4*>(sX)[t] =
            reinterpret_cast<const float4*>(x)[(size_t)(b * II + i) * 4 + r];
    }
    __syncthreads();

    const int bg = t >> 4, q = t & 15;
    u64 xr[4][8];
    #pragma unroll
    for (int s = 0; s < 4; s++) {
        const u64* xp = reinterpret_cast<const u64*>(sX + (bg + 16 * s) * CC);
        #pragma unroll
        for (int k = 0; k < 8; k++) xr[s][k] = xp[k];
    }

    __half2* Uo = reinterpret_cast<__half2*>(g_U);
    for (int j = 0; j < JJ; j++) {
        u64 w0[8], w1[8];
        const u64* r0 = reinterpret_cast<const u64*>(sW + (j * 32 + q * 2) * 18);
        const u64* r1 = reinterpret_cast<const u64*>(sW + (j * 32 + q * 2 + 1) * 18);
        #pragma unroll
        for (int k = 0; k < 8; k++) { w0[k] = r0[k]; w1[k] = r1[k]; }
        #pragma unroll
        for (int s = 0; s < 4; s++) {
            u64 a0 = 0ULL, a1 = 0ULL, b0 = 0ULL, b1 = 0ULL;
            #pragma unroll
            for (int k = 0; k < 8; k += 2) {
                a0 = fma2(w0[k],     xr[s][k],     a0);
                a1 = fma2(w0[k + 1], xr[s][k + 1], a1);
                b0 = fma2(w1[k],     xr[s][k],     b0);
                b1 = fma2(w1[k + 1], xr[s][k + 1], b1);
            }
            float d0 = hsum2(add2(a0, a1));
            float d1 = hsum2(add2(b0, b1));
            int b = bg + 16 * s;
            Uo[(size_t)(b * II + i) * 512 + j * 16 + q] = __floats2half2_rn(d0, d1);
        }
    }
}

// ---------------------------------------------------------------------------
// Kernel B: one fused routing pass over fp16 u_hat.
// grid = (NTILE, BB); 8 warps x 16 i each. Per (b,i): 2KB tile, lane l chunk m
// (uint4 = 8 halfs) holds j = 8m + (l>>2), d-seg (l&3)*8..+7.
// Logits reduced over 4-lane groups (xor 1,2); softmax over 32 j via in-thread
// max/sum over m plus xor 4,8,16. KIT==0: c = 1/32 exactly, no osum/softmax.
// Fixed-order block reduce -> deterministic, no atomics.
// ---------------------------------------------------------------------------
template <int KIT>
__global__ void __launch_bounds__(256, 2) route_kernel() {
    __shared__ float sS[8][JJ * DD];  // 32 KB
    const int itile = blockIdx.x, b = blockIdx.y;
    const int t = threadIdx.x, w = t >> 5, l = t & 31;

    float ov[4][8];
    if (KIT > 0) {
        const float4* op = reinterpret_cast<const float4*>(g_osum + b * (JJ * DD));
        #pragma unroll
        for (int m = 0; m < 4; m++) {
            float4 f0 = op[m * 64 + 2 * l], f1 = op[m * 64 + 2 * l + 1];
            ov[m][0] = f0.x; ov[m][1] = f0.y; ov[m][2] = f0.z; ov[m][3] = f0.w;
            ov[m][4] = f1.x; ov[m][5] = f1.y; ov[m][6] = f1.z; ov[m][7] = f1.w;
        }
    }
    float sacc[4][8];
    #pragma unroll
    for (int m = 0; m < 4; m++)
        #pragma unroll
        for (int k = 0; k < 8; k++) sacc[m][k] = 0.f;

    const uint4* Ub = reinterpret_cast<const uint4*>(g_U);
    const int i0 = itile * IPB + w * IPW;
    for (int n = 0; n < IPW; n++) {
        size_t base = ((size_t)b * II + (i0 + n)) * 128;
        uint4 r[4];
        #pragma unroll
        for (int m = 0; m < 4; m++) r[m] = Ub[base + m * 32 + l];
        float uf[4][8];
        #pragma unroll
        for (int m = 0; m < 4; m++) {
            const __half2* h = reinterpret_cast<const __half2*>(&r[m]);
            #pragma unroll
            for (int p = 0; p < 4; p++) {
                float2 f = __half22float2(h[p]);
                uf[m][2 * p] = f.x;
                uf[m][2 * p + 1] = f.y;
            }
        }
        float c[4];
        if (KIT == 0) {
            #pragma unroll
            for (int m = 0; m < 4; m++) c[m] = 0.03125f;
        } else {
            float tp[4];
            #pragma unroll
            for (int m = 0; m < 4; m++) {
                float a = uf[m][0] * ov[m][0];
                #pragma unroll
                for (int k = 1; k < 8; k++) a = fmaf(uf[m][k], ov[m][k], a);
                tp[m] = a;
            }
            #pragma unroll
            for (int s = 1; s < 4; s <<= 1)
                #pragma unroll
                for (int m = 0; m < 4; m++)
                    tp[m] += __shfl_xor_sync(0xffffffffu, tp[m], s);
            float mx = fmaxf(fmaxf(tp[0], tp[1]), fmaxf(tp[2], tp[3]));
            mx = fmaxf(mx, __shfl_xor_sync(0xffffffffu, mx, 4));
            mx = fmaxf(mx, __shfl_xor_sync(0xffffffffu, mx, 8));
            mx = fmaxf(mx, __shfl_xor_sync(0xffffffffu, mx, 16));
            float e[4], ss = 0.f;
            #pragma unroll
            for (int m = 0; m < 4; m++) {
                e[m] = __expf(tp[m] - mx);
                ss += e[m];
            }
            ss += __shfl_xor_sync(0xffffffffu, ss, 4);
            ss += __shfl_xor_sync(0xffffffffu, ss, 8);
            ss += __shfl_xor_sync(0xffffffffu, ss, 16);
            float inv = 1.0f / ss;
            #pragma unroll
            for (int m = 0; m < 4; m++) c[m] = e[m] * inv;
        }
        #pragma unroll
        for (int m = 0; m < 4; m++)
            #pragma unroll
            for (int k = 0; k < 8; k++) sacc[m][k] = fmaf(c[m], uf[m][k], sacc[m][k]);
    }

    float4* sp = reinterpret_cast<float4*>(sS[w]);
    #pragma unroll
    for (int m = 0; m < 4; m++) {
        sp[(m * 32 + l) * 2 + 0] =
            make_float4(sacc[m][0], sacc[m][1], sacc[m][2], sacc[m][3]);
        sp[(m * 32 + l) * 2 + 1] =
            make_float4(sacc[m][4], sacc[m][5], sacc[m][6], sacc[m][7]);
    }
    __syncthreads();
    for (int idx = t; idx < JJ * DD; idx += 256) {
        float v = sS[0][idx] + sS[1][idx] + sS[2][idx] + sS[3][idx] +
                  sS[4][idx] + sS[5][idx] + sS[6][idx] + sS[7][idx];
        g_spart[itile][b * (JJ * DD) + idx] = v;
    }
}

// ---------------------------------------------------------------------------
// Kernel C: reduce itile partials, squash, update osum / write final out.
// mode 0: osum = o ; mode 1: osum += o ; mode 2: out = o.
// One warp per (b,j); lane = d. Fixed reduction order -> deterministic.
// ---------------------------------------------------------------------------
__global__ void __launch_bounds__(256) squash_kernel(float* __restrict__ out,
                                                     int mode) {
    const int t = threadIdx.x;
    const int bj = blockIdx.x * 8 + (t >> 5);
    const int l = t & 31;
    float v = 0.f;
    #pragma unroll
    for (int it = 0; it < NTILE; it++) v += g_spart[it][bj * DD + l];
    float s2 = v * v;
    #pragma unroll
    for (int s = 1; s < 32; s <<= 1) s2 += __shfl_xor_sync(0xffffffffu, s2, s);
    float scale = (s2 / (1.0f + s2)) * rsqrtf(s2 + 1e-7f);
    float o = scale * v;
    if (mode == 2)
        out[bj * DD + l] = o;
    else if (mode == 1)
        g_osum[bj * DD + l] += o;
    else
        g_osum[bj * DD + l] = o;
}

// ---------------------------------------------------------------------------
extern "C" void kernel_launch(void* const* d_in, const int* in_sizes, int n_in,
                              void* d_out, int out_size) {
    const float* x;
    const float* W;
    if (in_sizes[0] == BB * II * CC) {
        x = (const float*)d_in[0];
        W = (const float*)d_in[1];
    } else {
        x = (const float*)d_in[1];
        W = (const float*)d_in[0];
    }

    const int smem_bytes = (1024 * 18 + BB * CC) * (int)sizeof(float);  // 77824
    cudaFuncSetAttribute(uhat_kernel, cudaFuncAttributeMaxDynamicSharedMemorySize,
                         smem_bytes);

    float* out = (float*)d_out;
    uhat_kernel<<<II, 256, smem_bytes>>>(x, W);
    route_kernel<0><<<dim3(NTILE, BB), 256>>>();
    squash_kernel<<<BB * JJ / 8, 256>>>(out, 0);
    route_kernel<1><<<dim3(NTILE, BB), 256>>>();
    squash_kernel<<<BB * JJ / 8, 256>>>(out, 1);
    route_kernel<2><<<dim3(NTILE, BB), 256>>>();
    squash_kernel<<<BB * JJ / 8, 256>>>(out, 2);
}

// round 3
// speedup vs baseline: 4.2691x; 1.0152x over previous
#include <cuda_runtime.h>
#include <cuda_fp16.h>

// CapsuleLayer dynamic routing, GB300 sm_103a.
// B=64, I=2048, Din=16, J=32, D=32, 3 routing iters.
//
// b_k[b,j,i] = osum_k[b,j,:] . u_hat[b,j,i,:]; each routing iteration is one
// streaming pass over fp16 u_hat ([b][i][j][d]) + tiny squash. Iteration 0 has
// c == 1/32 exactly. Softmax without max-subtraction (logits bounded, fp32 exp
// safe) to shorten the shuffle dependency chain.

#define BB 64
#define II 2048
#define CC 16     // Din
#define JJ 32
#define DD 32
#define NTILE 16  // i-tiles for routing partials
#define IPB 128   // i per routing block
#define IPW 16    // i per warp (8 warps/block)

typedef unsigned long long u64;

__device__ __half g_U[(size_t)BB * II * JJ * DD];   // 256 MB scratch (fp16)
__device__ float g_osum[BB * JJ * DD];              // running output sum
__device__ float g_spart[NTILE][BB * JJ * DD];      // per-itile partial s

// ---------- packed fp32x2 helpers (2x fp32 throughput on sm_103a) ----------
__device__ __forceinline__ u64 fma2(u64 a, u64 b, u64 c) {
    u64 d;
    asm("fma.rn.f32x2 %0, %1, %2, %3;" : "=l"(d) : "l"(a), "l"(b), "l"(c));
    return d;
}
__device__ __forceinline__ u64 add2(u64 a, u64 b) {
    u64 d;
    asm("add.rn.f32x2 %0, %1, %2;" : "=l"(d) : "l"(a), "l"(b));
    return d;
}
__device__ __forceinline__ float hsum2(u64 v) {
    float a, b;
    asm("mov.b64 {%0, %1}, %2;" : "=f"(a), "=f"(b) : "l"(v));
    return a + b;
}

// ---------------------------------------------------------------------------
// Kernel A: u_hat[b][i][j][d] = sum_c W[j][i][d][c] * x[b][i][c], stored fp16.
// One block per i. W staged in smem chunk-major: sW[k][row] (row = j*32+d,
// k = c-pair) as float2 -> per-(j,thread) read = 8 contiguous LDS.128
// (conflict-free, broadcast-deduped across the 2 batch-lanes).
// Thread (bg = t>>4, q = t&15): 4 batches (b = bg+16s), 2 d's (2q, 2q+1).
// ---------------------------------------------------------------------------
__global__ void __launch_bounds__(256, 2)
uhat_kernel(const float* __restrict__ x, const float* __restrict__ W) {
    extern __shared__ char smraw[];
    float2* sW = reinterpret_cast<float2*>(smraw);        // [8][1024] = 64KB
    float* sX = reinterpret_cast<float*>(smraw + 65536);  // [64][16]  = 4KB
    const int i = blockIdx.x;
    const int t = threadIdx.x;

    // Stage W slice (64KB): global float4 (4 c's) -> two float2 chunks.
    const float4* Wg = reinterpret_cast<const float4*>(W);
    #pragma unroll
    for (int k = 0; k < 16; k++) {
        int v = t + 256 * k;          // 0..4095
        int row = v >> 2, ch = v & 3; // row = j*32 + d
        int j = row >> 5, d = row & 31;
        float4 f = Wg[(size_t)(j * II + i) * 128 + d * 4 + ch];
        sW[(2 * ch) * 1024 + row] = make_float2(f.x, f.y);
        sW[(2 * ch + 1) * 1024 + row] = make_float2(f.z, f.w);
    }
    // Stage x slice (64 b x 16 c).
    {
        int b = t >> 2, r = t & 3;
        reinterpret_cast<float4*>(sX)[t] =
            reinterpret_cast<const float4*>(x)[(size_t)(b * II + i) * 4 + r];
    }
    __syncthreads();

    const int bg = t >> 4, q = t & 15;
    u64 xr[4][8];
    #pragma unroll
    for (int s = 0; s < 4; s++) {
        const u64* xp = reinterpret_cast<const u64*>(sX + (bg + 16 * s) * CC);
        #pragma unroll
        for (int k = 0; k < 8; k++) xr[s][k] = xp[k];
    }

    __half2* Uo = reinterpret_cast<__half2*>(g_U);
    const float4* sW4 = reinterpret_cast<const float4*>(sW);
    for (int j = 0; j < JJ; j++) {
        // 8 contiguous LDS.128: rows (j*32+2q, j*32+2q+1), chunk k.
        u64 w0[8], w1[8];
        #pragma unroll
        for (int k = 0; k < 8; k++) {
            float4 wv = sW4[k * 512 + j * 16 + q];
            const u64* pv = reinterpret_cast<const u64*>(&wv);
            w0[k] = pv[0];  // d = 2q,   c pair (2k, 2k+1)
            w1[k] = pv[1];  // d = 2q+1, c pair (2k, 2k+1)
        }
        #pragma unroll
        for (int s = 0; s < 4; s++) {
            u64 a0 = 0ULL, a1 = 0ULL, b0 = 0ULL, b1 = 0ULL;
            #pragma unroll
            for (int k = 0; k < 8; k += 2) {
                a0 = fma2(w0[k],     xr[s][k],     a0);
                a1 = fma2(w0[k + 1], xr[s][k + 1], a1);
                b0 = fma2(w1[k],     xr[s][k],     b0);
                b1 = fma2(w1[k + 1], xr[s][k + 1], b1);
            }
            float d0 = hsum2(add2(a0, a1));
            float d1 = hsum2(add2(b0, b1));
            int b = bg + 16 * s;
            Uo[(size_t)(b * II + i) * 512 + j * 16 + q] = __floats2half2_rn(d0, d1);
        }
    }
}

// ---------------------------------------------------------------------------
// Routing pass helpers.
// ---------------------------------------------------------------------------
__device__ __forceinline__ void cvt8(const uint4& r, float* uf) {
    const __half2* h = reinterpret_cast<const __half2*>(&r);
    #pragma unroll
    for (int p = 0; p < 4; p++) {
        float2 f = __half22float2(h[p]);
        uf[2 * p] = f.x;
        uf[2 * p + 1] = f.y;
    }
}

template <int KIT>
__device__ __forceinline__ void route_step(const uint4* r, const float ov[4][8],
                                           float sacc[4][8]) {
    float uf[4][8];
    #pragma unroll
    for (int m = 0; m < 4; m++) cvt8(r[m], uf[m]);
    float c[4];
    if (KIT == 0) {
        #pragma unroll
        for (int m = 0; m < 4; m++) c[m] = 0.03125f;
    } else {
        float tp[4];
        #pragma unroll
        for (int m = 0; m < 4; m++) {
            float a = uf[m][0] * ov[m][0];
            #pragma unroll
            for (int k = 1; k < 8; k++) a = fmaf(uf[m][k], ov[m][k], a);
            tp[m] = a;
        }
        #pragma unroll
        for (int s = 1; s < 4; s <<= 1)
            #pragma unroll
            for (int m = 0; m < 4; m++)
                tp[m] += __shfl_xor_sync(0xffffffffu, tp[m], s);
        // no max-subtraction: |logit| is small, fp32 exp is safe
        float e[4], ss = 0.f;
        #pragma unroll
        for (int m = 0; m < 4; m++) {
            e[m] = __expf(tp[m]);
            ss += e[m];
        }
        ss += __shfl_xor_sync(0xffffffffu, ss, 4);
        ss += __shfl_xor_sync(0xffffffffu, ss, 8);
        ss += __shfl_xor_sync(0xffffffffu, ss, 16);
        float inv = __fdividef(1.0f, ss);
        #pragma unroll
        for (int m = 0; m < 4; m++) c[m] = e[m] * inv;
    }
    #pragma unroll
    for (int m = 0; m < 4; m++)
        #pragma unroll
        for (int k = 0; k < 8; k++) sacc[m][k] = fmaf(c[m], uf[m][k], sacc[m][k]);
}

// ---------------------------------------------------------------------------
// Kernel B: one fused routing pass over fp16 u_hat, 2 i's in flight.
// grid = (NTILE, BB); 8 warps x 16 i each. Lane l chunk m (uint4 = 8 halfs):
// j = 8m + (l>>2), d-seg (l&3)*8..+7. Logit reduce over 4-lane groups; softmax
// over 32 j via in-thread + xor 4,8,16. Fixed-order reduce -> deterministic.
// ---------------------------------------------------------------------------
template <int KIT>
__global__ void __launch_bounds__(256, 2) route_kernel() {
    __shared__ float sS[8][JJ * DD];  // 32 KB
    const int itile = blockIdx.x, b = blockIdx.y;
    const int t = threadIdx.x, w = t >> 5, l = t & 31;

    float ov[4][8];
    if (KIT > 0) {
        const float4* op = reinterpret_cast<const float4*>(g_osum + b * (JJ * DD));
        #pragma unroll
        for (int m = 0; m < 4; m++) {
            float4 f0 = op[m * 64 + 2 * l], f1 = op[m * 64 + 2 * l + 1];
            ov[m][0] = f0.x; ov[m][1] = f0.y; ov[m][2] = f0.z; ov[m][3] = f0.w;
            ov[m][4] = f1.x; ov[m][5] = f1.y; ov[m][6] = f1.z; ov[m][7] = f1.w;
        }
    }
    float sacc[4][8];
    #pragma unroll
    for (int m = 0; m < 4; m++)
        #pragma unroll
        for (int k = 0; k < 8; k++) sacc[m][k] = 0.f;

    const uint4* Ub = reinterpret_cast<const uint4*>(g_U);
    const int i0 = itile * IPB + w * IPW;
    for (int n = 0; n < IPW; n += 2) {
        size_t base0 = ((size_t)b * II + (i0 + n)) * 128;
        uint4 r0[4], r1[4];
        #pragma unroll
        for (int m = 0; m < 4; m++) r0[m] = __ldg(Ub + base0 + m * 32 + l);
        #pragma unroll
        for (int m = 0; m < 4; m++) r1[m] = __ldg(Ub + base0 + 128 + m * 32 + l);
        route_step<KIT>(r0, ov, sacc);
        route_step<KIT>(r1, ov, sacc);
    }

    float4* sp = reinterpret_cast<float4*>(sS[w]);
    #pragma unroll
    for (int m = 0; m < 4; m++) {
        sp[(m * 32 + l) * 2 + 0] =
            make_float4(sacc[m][0], sacc[m][1], sacc[m][2], sacc[m][3]);
        sp[(m * 32 + l) * 2 + 1] =
            make_float4(sacc[m][4], sacc[m][5], sacc[m][6], sacc[m][7]);
    }
    __syncthreads();
    for (int idx = t; idx < JJ * DD; idx += 256) {
        float v = sS[0][idx] + sS[1][idx] + sS[2][idx] + sS[3][idx] +
                  sS[4][idx] + sS[5][idx] + sS[6][idx] + sS[7][idx];
        g_spart[itile][b * (JJ * DD) + idx] = v;
    }
}

// ---------------------------------------------------------------------------
// Kernel C: reduce itile partials, squash, update osum / write final out.
// mode 0: osum = o ; mode 1: osum += o ; mode 2: out = o.
// ---------------------------------------------------------------------------
__global__ void __launch_bounds__(256) squash_kernel(float* __restrict__ out,
                                                     int mode) {
    const int t = threadIdx.x;
    const int bj = blockIdx.x * 8 + (t >> 5);
    const int l = t & 31;
    float v = 0.f;
    #pragma unroll
    for (int it = 0; it < NTILE; it++) v += g_spart[it][bj * DD + l];
    float s2 = v * v;
    #pragma unroll
    for (int s = 1; s < 32; s <<= 1) s2 += __shfl_xor_sync(0xffffffffu, s2, s);
    float scale = (s2 / (1.0f + s2)) * rsqrtf(s2 + 1e-7f);
    float o = scale * v;
    if (mode == 2)
        out[bj * DD + l] = o;
    else if (mode == 1)
        g_osum[bj * DD + l] += o;
    else
        g_osum[bj * DD + l] = o;
}

// ---------------------------------------------------------------------------
extern "C" void kernel_launch(void* const* d_in, const int* in_sizes, int n_in,
                              void* d_out, int out_size) {
    const float* x;
    const float* W;
    if (in_sizes[0] == BB * II * CC) {
        x = (const float*)d_in[0];
        W = (const float*)d_in[1];
    } else {
        x = (const float*)d_in[1];
        W = (const float*)d_in[0];
    }

    const int smem_bytes = 65536 + BB * CC * (int)sizeof(float);  // 69632
    cudaFuncSetAttribute(uhat_kernel, cudaFuncAttributeMaxDynamicSharedMemorySize,
                         smem_bytes);

    float* out = (float*)d_out;
    uhat_kernel<<<II, 256, smem_bytes>>>(x, W);
    route_kernel<0><<<dim3(NTILE, BB), 256>>>();
    squash_kernel<<<BB * JJ / 8, 256>>>(out, 0);
    route_kernel<1><<<dim3(NTILE, BB), 256>>>();
    squash_kernel<<<BB * JJ / 8, 256>>>(out, 1);
    route_kernel<2><<<dim3(NTILE, BB), 256>>>();
    squash_kernel<<<BB * JJ / 8, 256>>>(out, 2);
}